// round 13
// baseline (speedup 1.0000x reference)
#include <cuda_runtime.h>
#include <cuda_fp16.h>
#include <cstdint>

// ============================================================================
// out[M,N] = ((x+66)*0.03) @ ((y-160)*0.025),  M=N=K=4096
// fp16 HMMA mma.sync.m16n8k16.f32.f16.f16.f32 (real HW on base sm_103).
// Centered values are integers <= 256 -> exact fp16; fp32 accumulation.
// R12: tensor=71.6%, 2 CTAs/SM, grid 1024 -> 3.46 waves (13.5% tail loss).
// R13: split-K2 -> grid (32,32,2)=2048 jobs, 6.92 waves (1.2% tail).
//   out = S*acc_k0 + S*acc_k1 via atomicAdd onto zeroed buffer.
//   Exactly 2 commutative fp32 adds per element -> deterministic.
//   d_out zeroing folded into prep_kernel (+2048 blocks).
// Mainloop & register budget unchanged (127 regs, 2 CTAs/SM).
// ============================================================================

#define MDIM 4096
#define NDIM 4096
#define KDIM 4096

#define BM 128
#define BN 128
#define BK 64
#define STAGES 3
#define KSPLIT 2
#define KITERS (KDIM / BK / KSPLIT)   // 32 per job
#define THREADS 256

#define A_STAGE_BYTES (BM * BK * 2)   // 16384
#define B_STAGE_BYTES (BN * BK * 2)   // 16384
#define STAGE_BYTES   (A_STAGE_BYTES + B_STAGE_BYTES)   // 32768
#define SMEM_TOTAL    (STAGES * STAGE_BYTES)            // 98304

#define KBLOCKS (KDIM / BK)           // 64
#define A_BLOCK_BYTES 16384           // per (mb,kb): 8 mtiles * 4 kt16 * 512
#define B_BLOCK_BYTES 16384           // per (nb,kb): 16 ntiles * 2 kt32 * 512

#define OUT_SCALE 0.00075f

// ---------------------------------------------------------------------------
// Scratch
// ---------------------------------------------------------------------------
__device__ uint8_t g_A[(size_t)MDIM * KDIM * 2];   // f16 (x+66), fragment-packed
__device__ uint8_t g_B[(size_t)NDIM * KDIM * 2];   // f16 (y-160), fragment-packed

// ---------------------------------------------------------------------------
// helpers
// ---------------------------------------------------------------------------
__device__ __forceinline__ uint32_t smem_to_u32(const void* p) {
    uint32_t a;
    asm("{ .reg .u64 t; cvta.to.shared.u64 t, %1; cvt.u32.u64 %0, t; }"
        : "=r"(a) : "l"(p));
    return a;
}

#define CP_ASYNC16(dst, src) \
    asm volatile("cp.async.cg.shared.global [%0], [%1], 16;" :: "r"(dst), "l"(src))
#define CP_COMMIT() asm volatile("cp.async.commit_group;" ::: "memory")
#define CP_WAIT(n)  asm volatile("cp.async.wait_group %0;" :: "n"(n) : "memory")

__device__ __forceinline__ void hmma16816(float* d, const uint32_t* a,
                                          uint32_t b0, uint32_t b1) {
    asm volatile(
        "mma.sync.aligned.m16n8k16.row.col.f32.f16.f16.f32 "
        "{%0,%1,%2,%3}, {%4,%5,%6,%7}, {%8,%9}, {%0,%1,%2,%3};"
        : "+f"(d[0]), "+f"(d[1]), "+f"(d[2]), "+f"(d[3])
        : "r"(a[0]), "r"(a[1]), "r"(a[2]), "r"(a[3]), "r"(b0), "r"(b1));
}

__device__ __forceinline__ uint32_t pack_half2(int lo, int hi) {
    uint32_t l = (uint32_t)__half_as_ushort(__int2half_rn(lo));
    uint32_t h = (uint32_t)__half_as_ushort(__int2half_rn(hi));
    return l | (h << 16);
}

// ---------------------------------------------------------------------------
// Fragment layouts (mma.m16n8k16.row.col):
// A elem (row,k) in m16k16 tile (512B):
//   lane = (row&7)*4 + ((k&7)>>1), reg = ((row>>3)&1) | (((k>>3)&1)<<1),
//   half = k&1 ; byte = lane*16 + reg*4 + half*2
// A gmem: (mb*KBLOCKS+kb)*16384 + (mtile*4 + kt16)*512 + byte
// B elem (n,k) packed n8 x k32 super-tile (512B), both k16 halves in one
// 16B lane chunk for single LDS.128:
//   lane = (n&7)*4 + ((k&7)>>1), kt16 = (k>>4)&1, reg = (k>>3)&1, half = k&1
//   byte = lane*16 + kt16*8 + reg*4 + half*2
// B gmem: (nb*KBLOCKS+kb)*16384 + (ntile*2 + kt32)*512 + byte
// ---------------------------------------------------------------------------

// ---------------------------------------------------------------------------
// Fused prep kernel. Grid 10496 blocks x 256 threads:
//   blocks [0,256):       pack x -> f16 (x+66)
//   blocks [256,8448):    pack y -> f16 (y-160), transposed (smem 32k x 64n)
//   blocks [8448,10496):  zero d_out (required by split-K atomicAdd)
// ---------------------------------------------------------------------------
__global__ void prep_kernel(const int* __restrict__ x, const int* __restrict__ y,
                            float* __restrict__ out) {
    __shared__ int s[32][65];
    int bid = blockIdx.x;
    int t = threadIdx.x;

    if (bid < 256) {
        int band = bid;
        int m0 = band * 16;
        int r = t >> 4;               // 0..15
        int kt = t & 15;
        int mb = band >> 3;
        int mtile = band & 7;
        const int4* __restrict__ row = (const int4*)(x + (size_t)(m0 + r) * KDIM);
        uint32_t mbase = (uint32_t)(mb * KBLOCKS) * A_BLOCK_BYTES;
        uint32_t reg = (uint32_t)((r >> 3) & 1);
        #pragma unroll 4
        for (int j = 0; j < 64; j++) {
            int w = kt + j * 16;      // int4 index; k = 4w
            int4 v = row[w];
            int k = w * 4;
            uint32_t kb = (uint32_t)(k >> 6);
            uint32_t kt16 = (uint32_t)((k >> 4) & 3);
            uint32_t rg = reg | (uint32_t)(((k >> 3) & 1) << 1);
            uint32_t lane0 = (uint32_t)(((r & 7) << 2) | ((k & 4) >> 1));
            uint32_t addr = mbase + kb * A_BLOCK_BYTES
                          + (((uint32_t)mtile * 4 + kt16) << 9)
                          + lane0 * 16 + rg * 4;
            *reinterpret_cast<uint32_t*>(g_A + addr)      = pack_half2(v.x + 66, v.y + 66);
            *reinterpret_cast<uint32_t*>(g_A + addr + 16) = pack_half2(v.z + 66, v.w + 66);
        }
    } else if (bid < 8448) {
        int bid2 = bid - 256;                 // 0..8191
        int n0 = (bid2 >> 7) * 64;
        int k0 = (bid2 & 127) * 32;
        #pragma unroll
        for (int i = 0; i < 8; i++) {
            int idx = t + i * 256;
            int kk = idx >> 6, nn = idx & 63;
            s[kk][nn] = y[(size_t)(k0 + kk) * NDIM + (n0 + nn)];
        }
        __syncthreads();
        #pragma unroll
        for (int i = 0; i < 2; i++) {
            int w = t + i * 256;              // 0..511
            int n = w >> 3;                   // local n 0..63
            int kg = w & 7;                   // local k quad
            int ng = n0 + n;
            int kgl = k0 + kg * 4;
            uint32_t p0 = pack_half2(s[kg * 4 + 0][n] - 160, s[kg * 4 + 1][n] - 160);
            uint32_t p1 = pack_half2(s[kg * 4 + 2][n] - 160, s[kg * 4 + 3][n] - 160);
            uint32_t nb = (uint32_t)(ng >> 7);
            uint32_t ntile = (uint32_t)((ng >> 3) & 15);
            uint32_t kb = (uint32_t)(kgl >> 6);
            uint32_t kt32 = (uint32_t)((kgl >> 5) & 1);
            uint32_t kt16 = (uint32_t)((kgl >> 4) & 1);
            uint32_t rg = (uint32_t)((kgl >> 3) & 1);
            uint32_t lane0 = (uint32_t)(((ng & 7) << 2) | ((kgl & 4) >> 1));
            uint32_t addr = (nb * KBLOCKS + kb) * B_BLOCK_BYTES
                          + (ntile * 2 + kt32) * 512
                          + lane0 * 16 + kt16 * 8 + rg * 4;
            *reinterpret_cast<uint32_t*>(g_B + addr)      = p0;
            *reinterpret_cast<uint32_t*>(g_B + addr + 16) = p1;
        }
    } else {
        // zero d_out: 16M floats = 4M float4; 2048 blocks * 256 thr * 8 float4
        int zb = bid - 8448;                  // 0..2047
        float4* p = reinterpret_cast<float4*>(out) + (size_t)zb * 2048;
        float4 z = make_float4(0.f, 0.f, 0.f, 0.f);
        #pragma unroll
        for (int i = 0; i < 8; i++)
            p[i * 256 + t] = z;
    }
}

// ---------------------------------------------------------------------------
// GEMM: 128x128 tile, K split in 2 (blockIdx.z). 256 threads = 8 warps
// (2m x 4n), warp tile 64x32. 2 CTAs resident per SM. Epilogue: atomicAdd.
// ---------------------------------------------------------------------------
__device__ __forceinline__ void load_stage(uint32_t sbase, const uint8_t* Ag,
                                           const uint8_t* Bg, int t) {
    #pragma unroll
    for (int i = 0; i < 4; i++) {
        int c = t + i * THREADS;
        CP_ASYNC16(sbase + c * 16, Ag + c * 16);
    }
    #pragma unroll
    for (int i = 0; i < 4; i++) {
        int c = t + i * THREADS;
        CP_ASYNC16(sbase + A_STAGE_BYTES + c * 16, Bg + c * 16);
    }
}

__global__ void __launch_bounds__(THREADS, 2)
gemm_kernel(float* __restrict__ out) {
    extern __shared__ uint8_t smem[];
    uint32_t sm0 = smem_to_u32(smem);
    int t = threadIdx.x;
    int wid = t >> 5;
    int lane = t & 31;
    int wm = wid & 1;                 // 2 warps along M (64 rows)
    int wn = wid >> 1;                // 4 warps along N (32 cols)

    int mb = blockIdx.y;
    int nb = blockIdx.x;
    int km = blockIdx.z;              // k-half
    const uint8_t* Ag = g_A + (size_t)(mb * KBLOCKS + km * KITERS) * A_BLOCK_BYTES;
    const uint8_t* Bg = g_B + (size_t)(nb * KBLOCKS + km * KITERS) * B_BLOCK_BYTES;

    float acc[4][4][4];
    #pragma unroll
    for (int i = 0; i < 4; i++)
        #pragma unroll
        for (int j = 0; j < 4; j++)
            #pragma unroll
            for (int c = 0; c < 4; c++) acc[i][j][c] = 0.0f;

    #pragma unroll
    for (int s = 0; s < STAGES - 1; s++) {
        load_stage(sm0 + s * STAGE_BYTES, Ag + (size_t)s * A_BLOCK_BYTES,
                   Bg + (size_t)s * B_BLOCK_BYTES, t);
        CP_COMMIT();
    }

    for (int i = 0; i < KITERS; i++) {
        CP_WAIT(STAGES - 2);
        __syncthreads();

        int s_idx = i;
        while (s_idx >= STAGES) s_idx -= STAGES;   // i % 3 without div
        uint32_t sA = sm0 + s_idx * STAGE_BYTES;
        uint32_t sB = sA + A_STAGE_BYTES;

        // prefetch next stage before compute
        int j = i + STAGES - 1;
        if (j < KITERS) {
            int sj = j;
            while (sj >= STAGES) sj -= STAGES;
            load_stage(sm0 + sj * STAGE_BYTES, Ag + (size_t)j * A_BLOCK_BYTES,
                       Bg + (size_t)j * B_BLOCK_BYTES, t);
        }
        CP_COMMIT();

        uint32_t a[4][4], b[4][4];
        #pragma unroll
        for (int ks = 0; ks < 4; ks++) {      // 4 x k16
            if ((ks & 1) == 0) {
                #pragma unroll
                for (int nj = 0; nj < 4; nj++) {
                    uint32_t off = sB + (((uint32_t)(wn * 4 + nj) * 2 + (ks >> 1)) << 9)
                                 + (uint32_t)lane * 16;
                    asm volatile("ld.shared.v4.b32 {%0,%1,%2,%3}, [%4];"
                                 : "=r"(b[nj][0]), "=r"(b[nj][1]),
                                   "=r"(b[nj][2]), "=r"(b[nj][3])
                                 : "r"(off));
                }
            }
            #pragma unroll
            for (int mi = 0; mi < 4; mi++) {
                uint32_t off = sA + (((uint32_t)(wm * 4 + mi) * 4 + ks) << 9)
                             + (uint32_t)lane * 16;
                asm volatile("ld.shared.v4.b32 {%0,%1,%2,%3}, [%4];"
                             : "=r"(a[mi][0]), "=r"(a[mi][1]),
                               "=r"(a[mi][2]), "=r"(a[mi][3])
                             : "r"(off));
            }
            #pragma unroll
            for (int mi = 0; mi < 4; mi++)
                #pragma unroll
                for (int nj = 0; nj < 4; nj++)
                    hmma16816(acc[mi][nj], a[mi],
                              b[nj][(ks & 1) * 2], b[nj][(ks & 1) * 2 + 1]);
        }
    }

    // ------- epilogue: scale + atomicAdd (2 commutative adds/element) ------
    int g = lane >> 2;
    int tg = lane & 3;
    int mBase = mb * BM + wm * 64;
    int nBase = nb * BN + wn * 32;

    #pragma unroll
    for (int mi = 0; mi < 4; mi++) {
        #pragma unroll
        for (int h = 0; h < 2; h++) {
            int m = mBase + mi * 16 + h * 8 + g;
            float* orow = out + (size_t)m * NDIM;
            #pragma unroll
            for (int nj = 0; nj < 4; nj++) {
                int n = nBase + nj * 8 + tg * 2;
                atomicAdd(orow + n,     OUT_SCALE * acc[mi][nj][h * 2 + 0]);
                atomicAdd(orow + n + 1, OUT_SCALE * acc[mi][nj][h * 2 + 1]);
            }
        }
    }
}

// ---------------------------------------------------------------------------
// Launch: 2 kernels (prep+zero, gemm split-K2)
// ---------------------------------------------------------------------------
extern "C" void kernel_launch(void* const* d_in, const int* in_sizes, int n_in,
                              void* d_out, int out_size) {
    const int* x = (const int*)d_in[0];
    const int* y = (const int*)d_in[1];
    float* out = (float*)d_out;

    cudaFuncSetAttribute(gemm_kernel, cudaFuncAttributeMaxDynamicSharedMemorySize,
                         SMEM_TOTAL);

    prep_kernel<<<256 + 8192 + 2048, 256>>>(x, y, out);
    gemm_kernel<<<dim3(NDIM / BN, MDIM / BM, KSPLIT), THREADS, SMEM_TOTAL>>>(out);
}

// round 14
// speedup vs baseline: 1.0647x; 1.0647x over previous
#include <cuda_runtime.h>
#include <cuda_fp16.h>
#include <cstdint>

// ============================================================================
// out[M,N] = ((x+66)*0.03) @ ((y-160)*0.025),  M=N=K=4096
// fp16 HMMA mma.sync.m16n8k16.f32.f16.f16.f32 (real HW on base sm_103).
// Centered values are integers <= 256 -> exact fp16; fp32 accumulation.
// R12 best: 2 CTAs/SM, grid 1024 -> 3.46 waves (tail loss ~15%).
// R13 split-K2-everything regressed (atomics+overhead on 100% of work).
// R14: HYBRID TAIL FILL -- tiles 0..863 full-K (plain stores, unchanged);
//   tiles 864..1023 (last in launch order) split into 2 K-halves -> 320
//   half-jobs that fill the partial 4th wave. 864 + 320 = 1184 = 4.0 x 296.
//   atomicAdd only for split tiles (rows 3456..4095); prep zeroes that
//   contiguous 10MB strip only.
// ============================================================================

#define MDIM 4096
#define NDIM 4096
#define KDIM 4096

#define BM 128
#define BN 128
#define BK 64
#define STAGES 3
#define THREADS 256

#define A_STAGE_BYTES (BM * BK * 2)   // 16384
#define B_STAGE_BYTES (BN * BK * 2)   // 16384
#define STAGE_BYTES   (A_STAGE_BYTES + B_STAGE_BYTES)   // 32768
#define SMEM_TOTAL    (STAGES * STAGE_BYTES)            // 98304

#define KBLOCKS (KDIM / BK)           // 64
#define A_BLOCK_BYTES 16384           // per (mb,kb): 8 mtiles * 4 kt16 * 512
#define B_BLOCK_BYTES 16384           // per (nb,kb): 16 ntiles * 2 kt32 * 512

#define FULL_TILES 864                // tiles with full K
#define SPLIT_TILES 160               // tiles 864..1023, split-K2
#define TOTAL_JOBS (FULL_TILES + 2 * SPLIT_TILES)   // 1184 = 4 * 296

#define OUT_SCALE 0.00075f

// ---------------------------------------------------------------------------
// Scratch
// ---------------------------------------------------------------------------
__device__ uint8_t g_A[(size_t)MDIM * KDIM * 2];   // f16 (x+66), fragment-packed
__device__ uint8_t g_B[(size_t)NDIM * KDIM * 2];   // f16 (y-160), fragment-packed

// ---------------------------------------------------------------------------
// helpers
// ---------------------------------------------------------------------------
__device__ __forceinline__ uint32_t smem_to_u32(const void* p) {
    uint32_t a;
    asm("{ .reg .u64 t; cvta.to.shared.u64 t, %1; cvt.u32.u64 %0, t; }"
        : "=r"(a) : "l"(p));
    return a;
}

#define CP_ASYNC16(dst, src) \
    asm volatile("cp.async.cg.shared.global [%0], [%1], 16;" :: "r"(dst), "l"(src))
#define CP_COMMIT() asm volatile("cp.async.commit_group;" ::: "memory")
#define CP_WAIT(n)  asm volatile("cp.async.wait_group %0;" :: "n"(n) : "memory")

__device__ __forceinline__ void hmma16816(float* d, const uint32_t* a,
                                          uint32_t b0, uint32_t b1) {
    asm volatile(
        "mma.sync.aligned.m16n8k16.row.col.f32.f16.f16.f32 "
        "{%0,%1,%2,%3}, {%4,%5,%6,%7}, {%8,%9}, {%0,%1,%2,%3};"
        : "+f"(d[0]), "+f"(d[1]), "+f"(d[2]), "+f"(d[3])
        : "r"(a[0]), "r"(a[1]), "r"(a[2]), "r"(a[3]), "r"(b0), "r"(b1));
}

__device__ __forceinline__ uint32_t pack_half2(int lo, int hi) {
    uint32_t l = (uint32_t)__half_as_ushort(__int2half_rn(lo));
    uint32_t h = (uint32_t)__half_as_ushort(__int2half_rn(hi));
    return l | (h << 16);
}

// ---------------------------------------------------------------------------
// Fragment layouts (mma.m16n8k16.row.col):
// A elem (row,k) in m16k16 tile (512B):
//   lane = (row&7)*4 + ((k&7)>>1), reg = ((row>>3)&1) | (((k>>3)&1)<<1),
//   half = k&1 ; byte = lane*16 + reg*4 + half*2
// A gmem: (mb*KBLOCKS+kb)*16384 + (mtile*4 + kt16)*512 + byte
// B elem (n,k) packed n8 x k32 super-tile (512B), both k16 halves in one
// 16B lane chunk for single LDS.128:
//   lane = (n&7)*4 + ((k&7)>>1), kt16 = (k>>4)&1, reg = (k>>3)&1, half = k&1
//   byte = lane*16 + kt16*8 + reg*4 + half*2
// B gmem: (nb*KBLOCKS+kb)*16384 + (ntile*2 + kt32)*512 + byte
// ---------------------------------------------------------------------------

// ---------------------------------------------------------------------------
// Fused prep kernel. Grid 8768 blocks x 256 threads:
//   blocks [0,256):      pack x -> f16 (x+66)
//   blocks [256,8448):   pack y -> f16 (y-160), transposed (smem 32k x 64n)
//   blocks [8448,8768):  zero out rows [3456,4096) (split-tile strip, 10MB)
// ---------------------------------------------------------------------------
__global__ void prep_kernel(const int* __restrict__ x, const int* __restrict__ y,
                            float* __restrict__ out) {
    __shared__ int s[32][65];
    int bid = blockIdx.x;
    int t = threadIdx.x;

    if (bid < 256) {
        int band = bid;
        int m0 = band * 16;
        int r = t >> 4;               // 0..15
        int kt = t & 15;
        int mb = band >> 3;
        int mtile = band & 7;
        const int4* __restrict__ row = (const int4*)(x + (size_t)(m0 + r) * KDIM);
        uint32_t mbase = (uint32_t)(mb * KBLOCKS) * A_BLOCK_BYTES;
        uint32_t reg = (uint32_t)((r >> 3) & 1);
        #pragma unroll 4
        for (int j = 0; j < 64; j++) {
            int w = kt + j * 16;      // int4 index; k = 4w
            int4 v = row[w];
            int k = w * 4;
            uint32_t kb = (uint32_t)(k >> 6);
            uint32_t kt16 = (uint32_t)((k >> 4) & 3);
            uint32_t rg = reg | (uint32_t)(((k >> 3) & 1) << 1);
            uint32_t lane0 = (uint32_t)(((r & 7) << 2) | ((k & 4) >> 1));
            uint32_t addr = mbase + kb * A_BLOCK_BYTES
                          + (((uint32_t)mtile * 4 + kt16) << 9)
                          + lane0 * 16 + rg * 4;
            *reinterpret_cast<uint32_t*>(g_A + addr)      = pack_half2(v.x + 66, v.y + 66);
            *reinterpret_cast<uint32_t*>(g_A + addr + 16) = pack_half2(v.z + 66, v.w + 66);
        }
    } else if (bid < 8448) {
        int bid2 = bid - 256;                 // 0..8191
        int n0 = (bid2 >> 7) * 64;
        int k0 = (bid2 & 127) * 32;
        #pragma unroll
        for (int i = 0; i < 8; i++) {
            int idx = t + i * 256;
            int kk = idx >> 6, nn = idx & 63;
            s[kk][nn] = y[(size_t)(k0 + kk) * NDIM + (n0 + nn)];
        }
        __syncthreads();
        #pragma unroll
        for (int i = 0; i < 2; i++) {
            int w = t + i * 256;              // 0..511
            int n = w >> 3;                   // local n 0..63
            int kg = w & 7;                   // local k quad
            int ng = n0 + n;
            int kgl = k0 + kg * 4;
            uint32_t p0 = pack_half2(s[kg * 4 + 0][n] - 160, s[kg * 4 + 1][n] - 160);
            uint32_t p1 = pack_half2(s[kg * 4 + 2][n] - 160, s[kg * 4 + 3][n] - 160);
            uint32_t nb = (uint32_t)(ng >> 7);
            uint32_t ntile = (uint32_t)((ng >> 3) & 15);
            uint32_t kb = (uint32_t)(kgl >> 6);
            uint32_t kt32 = (uint32_t)((kgl >> 5) & 1);
            uint32_t kt16 = (uint32_t)((kgl >> 4) & 1);
            uint32_t rg = (uint32_t)((kgl >> 3) & 1);
            uint32_t lane0 = (uint32_t)(((ng & 7) << 2) | ((kgl & 4) >> 1));
            uint32_t addr = (nb * KBLOCKS + kb) * B_BLOCK_BYTES
                          + (ntile * 2 + kt32) * 512
                          + lane0 * 16 + kt16 * 8 + rg * 4;
            *reinterpret_cast<uint32_t*>(g_B + addr)      = p0;
            *reinterpret_cast<uint32_t*>(g_B + addr + 16) = p1;
        }
    } else {
        // zero out rows [3456,4096): 640*4096 floats = 655360 float4
        // 320 blocks * 256 thr * 8 float4
        int zb = bid - 8448;                  // 0..319
        float4* p = reinterpret_cast<float4*>(out + (size_t)3456 * NDIM)
                  + (size_t)zb * 2048;
        float4 z = make_float4(0.f, 0.f, 0.f, 0.f);
        #pragma unroll
        for (int i = 0; i < 8; i++)
            p[i * 256 + t] = z;
    }
}

// ---------------------------------------------------------------------------
// GEMM: 1D grid of 1184 jobs.
//   jid < 864:  full-K tile (tile=jid), plain-store epilogue.
//   jid >= 864: half-K job of tile 864+(e%160), km=e/160, atomicAdd epilogue.
// 256 threads = 8 warps (2m x 4n), warp tile 64x32. 2 CTAs/SM.
// ---------------------------------------------------------------------------
__device__ __forceinline__ void load_stage(uint32_t sbase, const uint8_t* Ag,
                                           const uint8_t* Bg, int t) {
    #pragma unroll
    for (int i = 0; i < 4; i++) {
        int c = t + i * THREADS;
        CP_ASYNC16(sbase + c * 16, Ag + c * 16);
    }
    #pragma unroll
    for (int i = 0; i < 4; i++) {
        int c = t + i * THREADS;
        CP_ASYNC16(sbase + A_STAGE_BYTES + c * 16, Bg + c * 16);
    }
}

__global__ void __launch_bounds__(THREADS, 2)
gemm_kernel(float* __restrict__ out) {
    extern __shared__ uint8_t smem[];
    uint32_t sm0 = smem_to_u32(smem);
    int t = threadIdx.x;
    int wid = t >> 5;
    int lane = t & 31;
    int wm = wid & 1;                 // 2 warps along M (64 rows)
    int wn = wid >> 1;                // 4 warps along N (32 cols)

    // ---- job decode ----
    int jid = blockIdx.x;
    int tile, km, kiters;
    bool split;
    if (jid < FULL_TILES) {
        tile = jid; km = 0; kiters = KBLOCKS; split = false;
    } else {
        int e = jid - FULL_TILES;             // 0..319
        km = (e >= SPLIT_TILES) ? 1 : 0;
        tile = FULL_TILES + (e - km * SPLIT_TILES);
        kiters = KBLOCKS / 2; split = true;
    }
    int mb = tile >> 5;
    int nb = tile & 31;

    const uint8_t* Ag = g_A + (size_t)(mb * KBLOCKS + km * (KBLOCKS / 2)) * A_BLOCK_BYTES;
    const uint8_t* Bg = g_B + (size_t)(nb * KBLOCKS + km * (KBLOCKS / 2)) * B_BLOCK_BYTES;

    float acc[4][4][4];
    #pragma unroll
    for (int i = 0; i < 4; i++)
        #pragma unroll
        for (int j = 0; j < 4; j++)
            #pragma unroll
            for (int c = 0; c < 4; c++) acc[i][j][c] = 0.0f;

    #pragma unroll
    for (int s = 0; s < STAGES - 1; s++) {
        load_stage(sm0 + s * STAGE_BYTES, Ag + (size_t)s * A_BLOCK_BYTES,
                   Bg + (size_t)s * B_BLOCK_BYTES, t);
        CP_COMMIT();
    }

    for (int i = 0; i < kiters; i++) {
        CP_WAIT(STAGES - 2);
        __syncthreads();

        int s_idx = i;
        while (s_idx >= STAGES) s_idx -= STAGES;   // i % 3 without div
        uint32_t sA = sm0 + s_idx * STAGE_BYTES;
        uint32_t sB = sA + A_STAGE_BYTES;

        // prefetch next stage before compute
        int j = i + STAGES - 1;
        if (j < kiters) {
            int sj = j;
            while (sj >= STAGES) sj -= STAGES;
            load_stage(sm0 + sj * STAGE_BYTES, Ag + (size_t)j * A_BLOCK_BYTES,
                       Bg + (size_t)j * B_BLOCK_BYTES, t);
        }
        CP_COMMIT();

        uint32_t a[4][4], b[4][4];
        #pragma unroll
        for (int ks = 0; ks < 4; ks++) {      // 4 x k16
            if ((ks & 1) == 0) {
                #pragma unroll
                for (int nj = 0; nj < 4; nj++) {
                    uint32_t off = sB + (((uint32_t)(wn * 4 + nj) * 2 + (ks >> 1)) << 9)
                                 + (uint32_t)lane * 16;
                    asm volatile("ld.shared.v4.b32 {%0,%1,%2,%3}, [%4];"
                                 : "=r"(b[nj][0]), "=r"(b[nj][1]),
                                   "=r"(b[nj][2]), "=r"(b[nj][3])
                                 : "r"(off));
                }
            }
            #pragma unroll
            for (int mi = 0; mi < 4; mi++) {
                uint32_t off = sA + (((uint32_t)(wm * 4 + mi) * 4 + ks) << 9)
                             + (uint32_t)lane * 16;
                asm volatile("ld.shared.v4.b32 {%0,%1,%2,%3}, [%4];"
                             : "=r"(a[mi][0]), "=r"(a[mi][1]),
                               "=r"(a[mi][2]), "=r"(a[mi][3])
                             : "r"(off));
            }
            #pragma unroll
            for (int mi = 0; mi < 4; mi++)
                #pragma unroll
                for (int nj = 0; nj < 4; nj++)
                    hmma16816(acc[mi][nj], a[mi],
                              b[nj][(ks & 1) * 2], b[nj][(ks & 1) * 2 + 1]);
        }
    }

    // ---------------- epilogue ----------------
    int g = lane >> 2;
    int tg = lane & 3;
    int mBase = mb * BM + wm * 64;
    int nBase = nb * BN + wn * 32;

    if (!split) {
        #pragma unroll
        for (int mi = 0; mi < 4; mi++) {
            #pragma unroll
            for (int h = 0; h < 2; h++) {
                int m = mBase + mi * 16 + h * 8 + g;
                float* orow = out + (size_t)m * NDIM;
                #pragma unroll
                for (int nj = 0; nj < 4; nj++) {
                    int n = nBase + nj * 8 + tg * 2;
                    float2 o;
                    o.x = OUT_SCALE * acc[mi][nj][h * 2 + 0];
                    o.y = OUT_SCALE * acc[mi][nj][h * 2 + 1];
                    *reinterpret_cast<float2*>(orow + n) = o;
                }
            }
        }
    } else {
        // exactly 2 commutative fp32 adds per element onto zeroed strip
        #pragma unroll
        for (int mi = 0; mi < 4; mi++) {
            #pragma unroll
            for (int h = 0; h < 2; h++) {
                int m = mBase + mi * 16 + h * 8 + g;
                float* orow = out + (size_t)m * NDIM;
                #pragma unroll
                for (int nj = 0; nj < 4; nj++) {
                    int n = nBase + nj * 8 + tg * 2;
                    atomicAdd(orow + n,     OUT_SCALE * acc[mi][nj][h * 2 + 0]);
                    atomicAdd(orow + n + 1, OUT_SCALE * acc[mi][nj][h * 2 + 1]);
                }
            }
        }
    }
}

// ---------------------------------------------------------------------------
// Launch: 2 kernels (prep+strip-zero, gemm 1184 jobs)
// ---------------------------------------------------------------------------
extern "C" void kernel_launch(void* const* d_in, const int* in_sizes, int n_in,
                              void* d_out, int out_size) {
    const int* x = (const int*)d_in[0];
    const int* y = (const int*)d_in[1];
    float* out = (float*)d_out;

    cudaFuncSetAttribute(gemm_kernel, cudaFuncAttributeMaxDynamicSharedMemorySize,
                         SMEM_TOTAL);

    prep_kernel<<<256 + 8192 + 320, 256>>>(x, y, out);
    gemm_kernel<<<TOTAL_JOBS, THREADS, SMEM_TOTAL>>>(out);
}

// round 16
// speedup vs baseline: 1.1141x; 1.0464x over previous
#include <cuda_runtime.h>
#include <cuda_fp16.h>
#include <cstdint>

// ============================================================================
// out[M,N] = ((x+66)*0.03) @ ((y-160)*0.025),  M=N=K=4096
// fp16 HMMA mma.sync.m16n8k16.f32.f16.f16.f32 (real HW on base sm_103).
// Centered values are integers <= 256 -> exact fp16; fp32 accumulation.
// Ceiling: HMMA fp32-acc ~1024 MAC/cyc/SM -> GEMM floor ~235us.
// R12: tensor=71.6% (GEMM 315us). R13/R14 tail fixes failed -> in-wave focus.
// R15: revert to R12 grid (1024 full-K tiles, plain stores) + reschedule
//   mainloop: next-stage cp.async spread ACROSS the ks loop (2/thread after
//   each ks step's MMAs) instead of bunched at iteration head; ks0 B-fragment
//   loads issue immediately after the barrier. Shrinks the per-iteration
//   post-barrier tensor-idle bubble. No register growth (stays 2 CTAs/SM).
// ============================================================================

#define MDIM 4096
#define NDIM 4096
#define KDIM 4096

#define BM 128
#define BN 128
#define BK 64
#define STAGES 3
#define KITERS (KDIM / BK)            // 64
#define THREADS 256

#define A_STAGE_BYTES (BM * BK * 2)   // 16384
#define B_STAGE_BYTES (BN * BK * 2)   // 16384
#define STAGE_BYTES   (A_STAGE_BYTES + B_STAGE_BYTES)   // 32768
#define SMEM_TOTAL    (STAGES * STAGE_BYTES)            // 98304

#define KBLOCKS (KDIM / BK)           // 64
#define A_BLOCK_BYTES 16384           // per (mb,kb): 8 mtiles * 4 kt16 * 512
#define B_BLOCK_BYTES 16384           // per (nb,kb): 16 ntiles * 2 kt32 * 512

#define OUT_SCALE 0.00075f

// ---------------------------------------------------------------------------
// Scratch
// ---------------------------------------------------------------------------
__device__ uint8_t g_A[(size_t)MDIM * KDIM * 2];   // f16 (x+66), fragment-packed
__device__ uint8_t g_B[(size_t)NDIM * KDIM * 2];   // f16 (y-160), fragment-packed

// ---------------------------------------------------------------------------
// helpers
// ---------------------------------------------------------------------------
__device__ __forceinline__ uint32_t smem_to_u32(const void* p) {
    uint32_t a;
    asm("{ .reg .u64 t; cvta.to.shared.u64 t, %1; cvt.u32.u64 %0, t; }"
        : "=r"(a) : "l"(p));
    return a;
}

#define CP_ASYNC16(dst, src) \
    asm volatile("cp.async.cg.shared.global [%0], [%1], 16;" :: "r"(dst), "l"(src))
#define CP_COMMIT() asm volatile("cp.async.commit_group;" ::: "memory")
#define CP_WAIT(n)  asm volatile("cp.async.wait_group %0;" :: "n"(n) : "memory")

__device__ __forceinline__ void hmma16816(float* d, const uint32_t* a,
                                          uint32_t b0, uint32_t b1) {
    asm volatile(
        "mma.sync.aligned.m16n8k16.row.col.f32.f16.f16.f32 "
        "{%0,%1,%2,%3}, {%4,%5,%6,%7}, {%8,%9}, {%0,%1,%2,%3};"
        : "+f"(d[0]), "+f"(d[1]), "+f"(d[2]), "+f"(d[3])
        : "r"(a[0]), "r"(a[1]), "r"(a[2]), "r"(a[3]), "r"(b0), "r"(b1));
}

__device__ __forceinline__ uint32_t pack_half2(int lo, int hi) {
    uint32_t l = (uint32_t)__half_as_ushort(__int2half_rn(lo));
    uint32_t h = (uint32_t)__half_as_ushort(__int2half_rn(hi));
    return l | (h << 16);
}

// ---------------------------------------------------------------------------
// Fragment layouts (mma.m16n8k16.row.col):
// A elem (row,k) in m16k16 tile (512B):
//   lane = (row&7)*4 + ((k&7)>>1), reg = ((row>>3)&1) | (((k>>3)&1)<<1),
//   half = k&1 ; byte = lane*16 + reg*4 + half*2
// A gmem: (mb*KBLOCKS+kb)*16384 + (mtile*4 + kt16)*512 + byte
// B elem (n,k) packed n8 x k32 super-tile (512B), both k16 halves in one
// 16B lane chunk for single LDS.128:
//   lane = (n&7)*4 + ((k&7)>>1), kt16 = (k>>4)&1, reg = (k>>3)&1, half = k&1
//   byte = lane*16 + kt16*8 + reg*4 + half*2
// B gmem: (nb*KBLOCKS+kb)*16384 + (ntile*2 + kt32)*512 + byte
// ---------------------------------------------------------------------------

// ---------------------------------------------------------------------------
// Fused prep kernel. Grid 8448 blocks x 256 threads:
//   blocks [0,256):     pack x -> f16 (x+66)
//   blocks [256,8448):  pack y -> f16 (y-160), transposed (smem 32k x 64n)
// ---------------------------------------------------------------------------
__global__ void prep_kernel(const int* __restrict__ x, const int* __restrict__ y) {
    __shared__ int s[32][65];
    int bid = blockIdx.x;
    int t = threadIdx.x;

    if (bid < 256) {
        int band = bid;
        int m0 = band * 16;
        int r = t >> 4;               // 0..15
        int kt = t & 15;
        int mb = band >> 3;
        int mtile = band & 7;
        const int4* __restrict__ row = (const int4*)(x + (size_t)(m0 + r) * KDIM);
        uint32_t mbase = (uint32_t)(mb * KBLOCKS) * A_BLOCK_BYTES;
        uint32_t reg = (uint32_t)((r >> 3) & 1);
        #pragma unroll 4
        for (int j = 0; j < 64; j++) {
            int w = kt + j * 16;      // int4 index; k = 4w
            int4 v = row[w];
            int k = w * 4;
            uint32_t kb = (uint32_t)(k >> 6);
            uint32_t kt16 = (uint32_t)((k >> 4) & 3);
            uint32_t rg = reg | (uint32_t)(((k >> 3) & 1) << 1);
            uint32_t lane0 = (uint32_t)(((r & 7) << 2) | ((k & 4) >> 1));
            uint32_t addr = mbase + kb * A_BLOCK_BYTES
                          + (((uint32_t)mtile * 4 + kt16) << 9)
                          + lane0 * 16 + rg * 4;
            *reinterpret_cast<uint32_t*>(g_A + addr)      = pack_half2(v.x + 66, v.y + 66);
            *reinterpret_cast<uint32_t*>(g_A + addr + 16) = pack_half2(v.z + 66, v.w + 66);
        }
    } else {
        int bid2 = bid - 256;                 // 0..8191
        int n0 = (bid2 >> 7) * 64;
        int k0 = (bid2 & 127) * 32;
        #pragma unroll
        for (int i = 0; i < 8; i++) {
            int idx = t + i * 256;
            int kk = idx >> 6, nn = idx & 63;
            s[kk][nn] = y[(size_t)(k0 + kk) * NDIM + (n0 + nn)];
        }
        __syncthreads();
        #pragma unroll
        for (int i = 0; i < 2; i++) {
            int w = t + i * 256;              // 0..511
            int n = w >> 3;                   // local n 0..63
            int kg = w & 7;                   // local k quad
            int ng = n0 + n;
            int kgl = k0 + kg * 4;
            uint32_t p0 = pack_half2(s[kg * 4 + 0][n] - 160, s[kg * 4 + 1][n] - 160);
            uint32_t p1 = pack_half2(s[kg * 4 + 2][n] - 160, s[kg * 4 + 3][n] - 160);
            uint32_t nb = (uint32_t)(ng >> 7);
            uint32_t ntile = (uint32_t)((ng >> 3) & 15);
            uint32_t kb = (uint32_t)(kgl >> 6);
            uint32_t kt32 = (uint32_t)((kgl >> 5) & 1);
            uint32_t kt16 = (uint32_t)((kgl >> 4) & 1);
            uint32_t rg = (uint32_t)((kgl >> 3) & 1);
            uint32_t lane0 = (uint32_t)(((ng & 7) << 2) | ((kgl & 4) >> 1));
            uint32_t addr = (nb * KBLOCKS + kb) * B_BLOCK_BYTES
                          + (ntile * 2 + kt32) * 512
                          + lane0 * 16 + kt16 * 8 + rg * 4;
            *reinterpret_cast<uint32_t*>(g_B + addr)      = p0;
            *reinterpret_cast<uint32_t*>(g_B + addr + 16) = p1;
        }
    }
}

// ---------------------------------------------------------------------------
// GEMM: 128x128 per CTA, 256 threads = 8 warps (2m x 4n), warp tile 64x32.
// 2 CTAs resident per SM. Next-stage cp.async interleaved into the ks loop.
// ---------------------------------------------------------------------------
__device__ __forceinline__ void load_stage(uint32_t sbase, const uint8_t* Ag,
                                           const uint8_t* Bg, int t) {
    #pragma unroll
    for (int i = 0; i < 4; i++) {
        int c = t + i * THREADS;
        CP_ASYNC16(sbase + c * 16, Ag + c * 16);
        CP_ASYNC16(sbase + A_STAGE_BYTES + c * 16, Bg + c * 16);
    }
}

// one quarter of a stage: 1 A-chunk + 1 B-chunk per thread
__device__ __forceinline__ void load_quarter(uint32_t sbase, const uint8_t* Ag,
                                             const uint8_t* Bg, int t, int q) {
    int c = t + q * THREADS;
    CP_ASYNC16(sbase + c * 16, Ag + c * 16);
    CP_ASYNC16(sbase + A_STAGE_BYTES + c * 16, Bg + c * 16);
}

__global__ void __launch_bounds__(THREADS, 2)
gemm_kernel(float* __restrict__ out) {
    extern __shared__ uint8_t smem[];
    uint32_t sm0 = smem_to_u32(smem);
    int t = threadIdx.x;
    int wid = t >> 5;
    int lane = t & 31;
    int wm = wid & 1;                 // 2 warps along M (64 rows)
    int wn = wid >> 1;                // 4 warps along N (32 cols)

    int mb = blockIdx.y;
    int nb = blockIdx.x;
    const uint8_t* Ag = g_A + (size_t)(mb * KBLOCKS) * A_BLOCK_BYTES;
    const uint8_t* Bg = g_B + (size_t)(nb * KBLOCKS) * B_BLOCK_BYTES;

    float acc[4][4][4];
    #pragma unroll
    for (int i = 0; i < 4; i++)
        #pragma unroll
        for (int j = 0; j < 4; j++)
            #pragma unroll
            for (int c = 0; c < 4; c++) acc[i][j][c] = 0.0f;

    #pragma unroll
    for (int s = 0; s < STAGES - 1; s++) {
        load_stage(sm0 + s * STAGE_BYTES, Ag + (size_t)s * A_BLOCK_BYTES,
                   Bg + (size_t)s * B_BLOCK_BYTES, t);
        CP_COMMIT();
    }

    for (int i = 0; i < KITERS; i++) {
        CP_WAIT(STAGES - 2);
        __syncthreads();

        int s_idx = i;
        while (s_idx >= STAGES) s_idx -= STAGES;   // i % 3 without div
        uint32_t sA = sm0 + s_idx * STAGE_BYTES;
        uint32_t sB = sA + A_STAGE_BYTES;

        int j = i + STAGES - 1;
        bool pf = (j < KITERS);
        int sj = j;
        while (sj >= STAGES) sj -= STAGES;
        uint32_t sPre = sm0 + sj * STAGE_BYTES;
        const uint8_t* Aj = Ag + (size_t)j * A_BLOCK_BYTES;
        const uint8_t* Bj = Bg + (size_t)j * B_BLOCK_BYTES;

        uint32_t a[4][4], b[4][4];
        #pragma unroll
        for (int ks = 0; ks < 4; ks++) {      // 4 x k16
            if ((ks & 1) == 0) {
                // B super-tile v4 covers two k16 steps (kt32 = ks>>1)
                #pragma unroll
                for (int nj = 0; nj < 4; nj++) {
                    uint32_t off = sB + (((uint32_t)(wn * 4 + nj) * 2 + (ks >> 1)) << 9)
                                 + (uint32_t)lane * 16;
                    asm volatile("ld.shared.v4.b32 {%0,%1,%2,%3}, [%4];"
                                 : "=r"(b[nj][0]), "=r"(b[nj][1]),
                                   "=r"(b[nj][2]), "=r"(b[nj][3])
                                 : "r"(off));
                }
            }
            #pragma unroll
            for (int mi = 0; mi < 4; mi++) {
                uint32_t off = sA + (((uint32_t)(wm * 4 + mi) * 4 + ks) << 9)
                             + (uint32_t)lane * 16;
                asm volatile("ld.shared.v4.b32 {%0,%1,%2,%3}, [%4];"
                             : "=r"(a[mi][0]), "=r"(a[mi][1]),
                               "=r"(a[mi][2]), "=r"(a[mi][3])
                             : "r"(off));
            }
            #pragma unroll
            for (int mi = 0; mi < 4; mi++)
                #pragma unroll
                for (int nj = 0; nj < 4; nj++)
                    hmma16816(acc[mi][nj], a[mi],
                              b[nj][(ks & 1) * 2], b[nj][(ks & 1) * 2 + 1]);

            // interleave next-stage loads AFTER this ks step's MMAs
            if (pf) load_quarter(sPre, Aj, Bj, t, ks);
        }
        CP_COMMIT();
    }

    // ---------------- epilogue: scale only (operands pre-centered) ---------
    int g = lane >> 2;
    int tg = lane & 3;
    int mBase = mb * BM + wm * 64;
    int nBase = nb * BN + wn * 32;

    #pragma unroll
    for (int mi = 0; mi < 4; mi++) {
        #pragma unroll
        for (int h = 0; h < 2; h++) {
            int m = mBase + mi * 16 + h * 8 + g;
            float* orow = out + (size_t)m * NDIM;
            #pragma unroll
            for (int nj = 0; nj < 4; nj++) {
                int n = nBase + nj * 8 + tg * 2;
                float2 o;
                o.x = OUT_SCALE * acc[mi][nj][h * 2 + 0];
                o.y = OUT_SCALE * acc[mi][nj][h * 2 + 1];
                *reinterpret_cast<float2*>(orow + n) = o;
            }
        }
    }
}

// ---------------------------------------------------------------------------
// Launch: 2 kernels (prep, gemm)
// ---------------------------------------------------------------------------
extern "C" void kernel_launch(void* const* d_in, const int* in_sizes, int n_in,
                              void* d_out, int out_size) {
    const int* x = (const int*)d_in[0];
    const int* y = (const int*)d_in[1];
    float* out = (float*)d_out;

    cudaFuncSetAttribute(gemm_kernel, cudaFuncAttributeMaxDynamicSharedMemorySize,
                         SMEM_TOTAL);

    prep_kernel<<<256 + 8192, 256>>>(x, y);
    gemm_kernel<<<dim3(NDIM / BN, MDIM / BM), THREADS, SMEM_TOTAL>>>(out);
}